// round 13
// baseline (speedup 1.0000x reference)
#include <cuda_runtime.h>
#include <cuda_bf16.h>
#include <math.h>
#include <stdint.h>

#define NN 30000
#define NE 180000
#define HD 128

#define BM 128
#define BK 32
#define BN 128
#define XLD 36
#define HLD 132
#define THREADS 512

// ---- enc/dec shared memory layout (floats) ----
#define SM_HS   0
#define SM_WS   (SM_HS + BM*HLD)
#define SM_XS   (SM_WS + BN*BN)
#define SM_BS   (SM_XS + BM*XLD)
#define SM_X3   (SM_BS + BN)
#define SM_IDX  (SM_X3 + BM*4)
#define SMEM_FLOATS (SM_IDX + 2*BM)
#define SMEM_BYTES (SMEM_FLOATS * 4)

// ---- blk mma kernel smem layout (bytes), single buffer ----
#define OFF_AL  16384
#define OFF_BH  32768
#define OFF_BL  49152
#define MB_B1   65536
#define MB_B2   66048
#define MB_SS   66560
#define MB_SR   67072
#define MMA_SMEM 67584

#define EBLK ((NE + BM - 1) / BM)   // 1407
#define NBLK ((NN + BM - 1) / BM)   // 235
#define ESTAT ((NE + 255) / 256)
#define NSTAT ((NN + 255) / 256)

typedef unsigned long long ull;

// ---------------- device scratch ----------------
// ef/nf stored SPLIT: row = [hi bf16 x128 | lo bf16 x128], value = hi + lo
__device__ __nv_bfloat16 g_ef_s[(size_t)NE * 256];
__device__ __nv_bfloat16 g_nf_s[(size_t)NN * 256];
__device__ float  g_agg[(size_t)NN * HD];
__device__ float  g_efraw[(size_t)NE * 3];
__device__ int    g_send[NE];
__device__ int    g_recv[NE];
__device__ double g_acc[32];
__device__ int    g_is64;

// pre-transposed bf16 hi/lo weights: layout [blk][n (128)][k]
__device__ __nv_bfloat16 g_wE1h[4*384*128], g_wE1l[4*384*128];
__device__ __nv_bfloat16 g_wE2h[4*128*128], g_wE2l[4*128*128];
__device__ __nv_bfloat16 g_wN1h[4*256*128], g_wN1l[4*256*128];
__device__ __nv_bfloat16 g_wN2h[4*128*128], g_wN2l[4*128*128];

// ---------------- f32x2 helpers ----------------
__device__ __forceinline__ ull pk2(float x, float y) {
    ull r; asm("mov.b64 %0, {%1, %2};" : "=l"(r) : "f"(x), "f"(y)); return r;
}
__device__ __forceinline__ void unpk2(ull v, float& x, float& y) {
    asm("mov.b64 {%0, %1}, %2;" : "=f"(x), "=f"(y) : "l"(v));
}
__device__ __forceinline__ ull fma2(ull a, ull b, ull c) {
    ull d; asm("fma.rn.f32x2 %0, %1, %2, %3;" : "=l"(d) : "l"(a), "l"(b), "l"(c)); return d;
}
__device__ __forceinline__ double wred(double v) {
    #pragma unroll
    for (int o = 16; o; o >>= 1) v += __shfl_down_sync(0xffffffffu, v, o);
    return v;
}

// ---------------- warp-mma helpers ----------------
__device__ __forceinline__ uint32_t smem_u32(const void* p) {
    uint32_t a;
    asm("{ .reg .u64 t; cvta.to.shared.u64 t, %1; cvt.u32.u64 %0, t; }" : "=r"(a) : "l"(p));
    return a;
}
__device__ __forceinline__ void ldsm4(uint32_t r[4], uint32_t addr) {
    asm volatile("ldmatrix.sync.aligned.m8n8.x4.shared.b16 {%0,%1,%2,%3}, [%4];"
        : "=r"(r[0]), "=r"(r[1]), "=r"(r[2]), "=r"(r[3]) : "r"(addr));
}
__device__ __forceinline__ void mma16816(float c[4], const uint32_t a[4], uint32_t b0, uint32_t b1) {
    asm volatile("mma.sync.aligned.m16n8k16.row.col.f32.bf16.bf16.f32 "
        "{%0,%1,%2,%3}, {%4,%5,%6,%7}, {%8,%9}, {%0,%1,%2,%3};"
        : "+f"(c[0]), "+f"(c[1]), "+f"(c[2]), "+f"(c[3])
        : "r"(a[0]), "r"(a[1]), "r"(a[2]), "r"(a[3]), "r"(b0), "r"(b1));
}
__device__ __forceinline__ uint32_t swz(uint32_t o) { return o ^ ((o >> 3) & 0x70); }
__device__ __forceinline__ uint32_t pkbf(float a, float b) {
    __nv_bfloat162 t = __floats2bfloat162_rn(a, b);
    return *(uint32_t*)&t;
}
__device__ __forceinline__ float2 upbf2(uint32_t u) {
    __nv_bfloat162 t = *(__nv_bfloat162*)&u;
    return make_float2(__bfloat162float(t.x), __bfloat162float(t.y));
}

// one 64-k slab of MMA over AH/AL vs BH/BL (hi*hi + hi*lo + lo*hi)
__device__ __forceinline__ void mma_slab(float acc[2][4][4], uint32_t abase,
                                         int wm, int wn, int lid) {
    #pragma unroll
    for (int k16 = 0; k16 < 4; k16++) {
        int kbA = k16*32 + ((lid >> 4) << 4);
        int rA  = lid & 15;
        uint32_t a0 = abase + swz((uint32_t)((wm*32 + rA)*128 + kbA));
        uint32_t a1 = abase + swz((uint32_t)((wm*32 + 16 + rA)*128 + kbA));
        uint32_t ah0[4], ah1[4], al0[4], al1[4];
        ldsm4(ah0, a0);           ldsm4(ah1, a1);
        ldsm4(al0, a0 + OFF_AL);  ldsm4(al1, a1 + OFF_AL);

        int g   = lid >> 3;
        int rB  = wn*32 + ((g >> 1) << 3) + (lid & 7);
        int kbB = k16*32 + ((g & 1) << 4);
        uint32_t b01 = abase + OFF_BH + swz((uint32_t)(rB*128 + kbB));
        uint32_t b23 = abase + OFF_BH + swz((uint32_t)((rB + 16)*128 + kbB));
        uint32_t bh01[4], bh23[4], bl01[4], bl23[4];
        ldsm4(bh01, b01);           ldsm4(bh23, b23);
        ldsm4(bl01, b01 + 16384);   ldsm4(bl23, b23 + 16384);

        #pragma unroll
        for (int ma = 0; ma < 2; ma++) {
            const uint32_t* ah = ma ? ah1 : ah0;
            const uint32_t* al = ma ? al1 : al0;
            mma16816(acc[ma][0], ah, bh01[0], bh01[1]);
            mma16816(acc[ma][0], ah, bl01[0], bl01[1]);
            mma16816(acc[ma][0], al, bh01[0], bh01[1]);
            mma16816(acc[ma][1], ah, bh01[2], bh01[3]);
            mma16816(acc[ma][1], ah, bl01[2], bl01[3]);
            mma16816(acc[ma][1], al, bh01[2], bh01[3]);
            mma16816(acc[ma][2], ah, bh23[0], bh23[1]);
            mma16816(acc[ma][2], ah, bl23[0], bl23[1]);
            mma16816(acc[ma][2], al, bh23[0], bh23[1]);
            mma16816(acc[ma][3], ah, bh23[2], bh23[3]);
            mma16816(acc[ma][3], ah, bl23[2], bl23[3]);
            mma16816(acc[ma][3], al, bh23[2], bh23[3]);
        }
    }
}

// stage one 64-k slab: A gather (pure 16B copies from split arrays) + W slab, LDG+STS
template<bool IS_EDGE>
__device__ __forceinline__ void stage_slab(char* smem, int kt,
                                           int row0, int M, const int* sSl, const int* sRl,
                                           const __nv_bfloat16* w1h, const __nv_bfloat16* w1l,
                                           int KIN, int tid) {
    if (!IS_EDGE && kt >= 2) {
        // agg slabs: manual fp32 -> bf16 hi/lo (source is fp32 atomics buffer)
        #pragma unroll
        for (int q = 0; q < 4; q++) {
            int f = tid + q * THREADS;         // 0..2047
            int rr = f >> 4, c4 = (f & 15) << 2;
            int gr = min(row0 + rr, M - 1);
            float4 v = *(const float4*)&g_agg[(size_t)gr*HD + (kt - 2)*64 + c4];
            __nv_bfloat16 h0 = __float2bfloat16_rn(v.x), h1 = __float2bfloat16_rn(v.y);
            __nv_bfloat16 h2 = __float2bfloat16_rn(v.z), h3 = __float2bfloat16_rn(v.w);
            uint2 uh = make_uint2(
                ((uint32_t)__bfloat16_as_ushort(h1) << 16) | __bfloat16_as_ushort(h0),
                ((uint32_t)__bfloat16_as_ushort(h3) << 16) | __bfloat16_as_ushort(h2));
            uint2 ul = make_uint2(
                pkbf(v.x - __bfloat162float(h0), v.y - __bfloat162float(h1)),
                pkbf(v.z - __bfloat162float(h2), v.w - __bfloat162float(h3)));
            uint32_t o = swz((uint32_t)(rr * 128 + c4 * 2));
            *(uint2*)(smem + o) = uh;
            *(uint2*)(smem + OFF_AL + o) = ul;
        }
    } else {
        // pure byte copy: hi and lo 16B chunks
        #pragma unroll
        for (int q = 0; q < 4; q++) {
            int f = tid + q * THREADS;         // 0..2047
            int rr = f >> 4, ch = f & 15;
            int gr = min(row0 + rr, M - 1);
            const __nv_bfloat16* rowp;
            if (IS_EDGE) {
                if (kt < 2)      rowp = g_ef_s + (size_t)gr * 256;
                else if (kt < 4) rowp = g_nf_s + (size_t)sSl[rr] * 256;
                else             rowp = g_nf_s + (size_t)sRl[rr] * 256;
            } else {
                rowp = g_nf_s + (size_t)gr * 256;
            }
            int hi = (ch < 8), c8 = ch & 7;
            uint4 v = __ldg((const uint4*)(rowp + (hi ? 0 : 128) + (kt & 1) * 64 + c8 * 8));
            uint32_t o = (hi ? 0u : (uint32_t)OFF_AL) + swz((uint32_t)(rr * 128 + c8 * 16));
            *(uint4*)(smem + o) = v;
        }
    }
    // W slab (hi + lo)
    #pragma unroll
    for (int q = 0; q < 2; q++) {
        int f = tid + q * THREADS;             // 0..1023
        int n = f >> 3, ch = f & 7;
        uint4 vh = __ldg((const uint4*)(w1h + (size_t)n * KIN + kt * 64 + ch * 8));
        uint4 vl = __ldg((const uint4*)(w1l + (size_t)n * KIN + kt * 64 + ch * 8));
        uint32_t o = OFF_BH + swz((uint32_t)(n * 128 + ch * 16));
        *(uint4*)(smem + o) = vh;
        *(uint4*)(smem + o + 16384) = vl;
    }
}

// ---------------- launch 1: detect idx dtype + zero g_acc ----------------
__global__ void detect_idx_kernel(const int* __restrict__ s) {
    __shared__ int red;
    int tid = threadIdx.x;
    if (tid < 32) g_acc[tid] = 0.0;
    if (tid == 0) red = 0;
    __syncthreads();
    int any = 0;
    for (int i = tid; i < 8192; i += 256) any |= s[2*i + 1];
    if (any) atomicOr(&red, 1);
    __syncthreads();
    if (tid == 0) g_is64 = red ? 0 : 1;
}

// ---------------- weight transpose + bf16 hi/lo split ----------------
__global__ void prep_w_kernel(const float* __restrict__ eW1, const float* __restrict__ eW2,
                              const float* __restrict__ nW1, const float* __restrict__ nW2) {
    int i = blockIdx.x * 512 + threadIdx.x;   // [0, 458752)
    float v; __nv_bfloat16* dh; __nv_bfloat16* dl; int di;
    if (i < 196608) {                         // edge W1: [4][384][128]
        int b = i / 49152, j = i % 49152, k = j >> 7, n = j & 127;
        v = eW1[i]; di = b*49152 + n*384 + k; dh = g_wE1h; dl = g_wE1l;
    } else if (i < 262144) {                  // edge W2: [4][128][128]
        int j = (i - 196608), b = j / 16384; j %= 16384;
        int k = j >> 7, n = j & 127;
        v = eW2[i - 196608]; di = b*16384 + n*128 + k; dh = g_wE2h; dl = g_wE2l;
    } else if (i < 393216) {                  // node W1: [4][256][128]
        int j = (i - 262144), b = j / 32768; j %= 32768;
        int k = j >> 7, n = j & 127;
        v = nW1[i - 262144]; di = b*32768 + n*256 + k; dh = g_wN1h; dl = g_wN1l;
    } else {                                  // node W2
        int j = (i - 393216), b = j / 16384; j %= 16384;
        int k = j >> 7, n = j & 127;
        v = nW2[i - 393216]; di = b*16384 + n*128 + k; dh = g_wN2h; dl = g_wN2l;
    }
    __nv_bfloat16 h = __float2bfloat16_rn(v);
    dh[di] = h;
    dl[di] = __float2bfloat16_rn(v - __bfloat162float(h));
}

// ---------------- convert idx + zero g_agg ----------------
__global__ void convert_idx_kernel(const int* __restrict__ s, const int* __restrict__ r) {
    int i = blockIdx.x * 256 + threadIdx.x;
    if (i < NE) {
        int w = g_is64 ? 2*i : i;
        g_send[i] = min(max(s[w], 0), NN - 1);
        g_recv[i] = min(max(r[w], 0), NN - 1);
    }
    const int total4 = NN * HD / 4;
    float4 z4 = make_float4(0.f, 0.f, 0.f, 0.f);
    for (int j = blockIdx.x * 256 + threadIdx.x; j < total4; j += ESTAT * 256)
        ((float4*)g_agg)[j] = z4;
}

// ---------------- fused edge+node stats ----------------
__global__ void stats_kernel(const float* __restrict__ pos, const float* __restrict__ zl,
                             const float* __restrict__ zt) {
    __shared__ double sm[12][8];
    int tid = threadIdx.x, w = tid >> 5, l = tid & 31;
    int b = blockIdx.x;
    if (b < ESTAT) {
        int e = b * 256 + tid;
        double v[6] = {0, 0, 0, 0, 0, 0};
        if (e < NE) {
            int s = g_send[e], r = g_recv[e];
            float rx = pos[2*s]   - pos[2*r];
            float ry = pos[2*s+1] - pos[2*r+1];
            float nn = sqrtf(rx*rx + ry*ry);
            g_efraw[3*e] = rx; g_efraw[3*e+1] = ry; g_efraw[3*e+2] = nn;
            v[0] = rx; v[1] = ry; v[2] = nn;
            v[3] = (double)rx*rx; v[4] = (double)ry*ry; v[5] = (double)nn*nn;
        }
        #pragma unroll
        for (int i = 0; i < 6; i++) { double rv = wred(v[i]); if (l == 0) sm[i][w] = rv; }
        __syncthreads();
        if (tid < 6) {
            double t = 0;
            #pragma unroll
            for (int j = 0; j < 8; j++) t += sm[tid][j];
            atomicAdd(&g_acc[tid], t);
        }
    } else {
        int n = (b - ESTAT) * 256 + tid;
        double v[12];
        #pragma unroll
        for (int i = 0; i < 12; i++) v[i] = 0;
        if (n < NN) {
            #pragma unroll
            for (int c = 0; c < 3; c++) {
                float a = zl[n*3 + c];
                float t = zt[n*3 + c] - a;
                v[c] = a; v[3+c] = (double)a*a; v[6+c] = t; v[9+c] = (double)t*t;
            }
        }
        #pragma unroll
        for (int i = 0; i < 12; i++) { double rv = wred(v[i]); if (l == 0) sm[i][w] = rv; }
        __syncthreads();
        if (tid < 12) {
            double t = 0;
            #pragma unroll
            for (int j = 0; j < 8; j++) t += sm[tid][j];
            atomicAdd(&g_acc[6 + tid], t);
        }
    }
}

// ---------------- f32x2 GEMM inner (enc/dec) ----------------
template<int LDA>
__device__ __forceinline__ void gemm84(ull acc[8][2], const float* __restrict__ A,
                                       const float* __restrict__ Ws, int tr, int tc) {
    #pragma unroll
    for (int k4 = 0; k4 < BK; k4 += 4) {
        float4 af[8];
        #pragma unroll
        for (int i = 0; i < 8; i++)
            af[i] = *(const float4*)&A[(tr*8 + i) * LDA + k4];
        #pragma unroll
        for (int s = 0; s < 4; s++) {
            float4 b = *(const float4*)&Ws[(k4 + s) * BN + tc*4];
            ull bp0 = pk2(b.x, b.y), bp1 = pk2(b.z, b.w);
            #pragma unroll
            for (int i = 0; i < 8; i++) {
                float av = (s == 0) ? af[i].x : (s == 1) ? af[i].y : (s == 2) ? af[i].z : af[i].w;
                ull a2 = pk2(av, av);
                acc[i][0] = fma2(a2, bp0, acc[i][0]);
                acc[i][1] = fma2(a2, bp1, acc[i][1]);
            }
        }
    }
}

__device__ __forceinline__ void load_W_tile(float* Ws, const float* __restrict__ W, int kt, int tid) {
    const float* wp = W + (size_t)kt * BK * BN;
    #pragma unroll
    for (int q = 0; q < 2; q++) {
        int f = tid + q * THREADS;
        int rr = f >> 5, cc = (f & 31) << 2;
        *(float4*)&Ws[rr * BN + cc] = __ldg((const float4*)&wp[rr * BN + cc]);
    }
}

__device__ __forceinline__ void load_W_full(float* Ws, const float* __restrict__ W, int tid) {
    #pragma unroll
    for (int q = 0; q < 8; q++) {
        int f = tid + q * THREADS;
        int rr = f >> 5, cc = (f & 31) << 2;
        *(float4*)&Ws[rr * BN + cc] = __ldg((const float4*)&W[rr * BN + cc]);
    }
}

// ---------------- fused encoders (f32x2 path, split output) ----------------
__global__ void __launch_bounds__(THREADS, 1)
enc_kernel(const float* __restrict__ enW1, const float* __restrict__ enb1,
           const float* __restrict__ enW2, const float* __restrict__ enb2,
           const float* __restrict__ eeW1, const float* __restrict__ eeb1,
           const float* __restrict__ eeW2, const float* __restrict__ eeb2,
           const float* __restrict__ zl) {
    extern __shared__ float smf[];
    float* Hs  = smf + SM_HS;
    float* Ws  = smf + SM_WS;
    float* bs  = smf + SM_BS;
    float* x3  = smf + SM_X3;
    float* w1s = smf + SM_XS;
    float* b1s = w1s + 384;

    bool isEdge = blockIdx.x < EBLK;
    int  row0   = (isEdge ? blockIdx.x : blockIdx.x - EBLK) * BM;
    int  M      = isEdge ? NE : NN;
    const float* W1 = isEdge ? eeW1 : enW1;
    const float* b1 = isEdge ? eeb1 : enb1;
    const float* W2 = isEdge ? eeW2 : enW2;
    const float* b2 = isEdge ? eeb2 : enb2;

    int tid = threadIdx.x;
    int tr = tid >> 5, tc = tid & 31;

    if (tid < 3 * BN) w1s[tid] = __ldg(&W1[tid]);
    else if (tid < 4 * BN) b1s[tid - 3*BN] = __ldg(&b1[tid - 3*BN]);
    if (tid < BN) bs[tid] = __ldg(&b2[tid]);
    if (tid >= THREADS - BM) {
        int t = tid - (THREADS - BM);
        int r = min(row0 + t, M - 1);
        int base = isEdge ? 0 : 6;
        double cnt = isEdge ? (double)NE : (double)NN;
        const float* src = isEdge ? (g_efraw + (size_t)3*r) : (zl + (size_t)3*r);
        #pragma unroll
        for (int k = 0; k < 3; k++) {
            double m = g_acc[base + k] / cnt, q = g_acc[base + 3 + k] / cnt;
            double sd = fmax(sqrt(fmax(q - m*m, 0.0)), 1e-8);
            x3[t*4 + k] = (src[k] - (float)m) / (float)sd;
        }
    }
    load_W_full(Ws, W2, tid);
    __syncthreads();

    #pragma unroll
    for (int i = 0; i < 8; i++) {
        int r = tr*8 + i;
        float x0 = x3[r*4], x1 = x3[r*4+1], x2 = x3[r*4+2];
        float4 h;
        float* hp = &h.x;
        #pragma unroll
        for (int j = 0; j < 4; j++) {
            int c = tc*4 + j;
            hp[j] = fmaxf(b1s[c] + x0*w1s[c] + x1*w1s[BN + c] + x2*w1s[2*BN + c], 0.f);
        }
        *(float4*)&Hs[r*HLD + tc*4] = h;
    }
    __syncthreads();

    ull acc[8][2];
    #pragma unroll
    for (int i = 0; i < 8; i++) { acc[i][0] = 0ull; acc[i][1] = 0ull; }
    #pragma unroll
    for (int kt = 0; kt < 4; kt++)
        gemm84<HLD>(acc, Hs + kt * BK, Ws + kt * BK * BN, tr, tc);

    __nv_bfloat16* dst = isEdge ? g_ef_s : g_nf_s;
    float4 bsv = *(float4*)&bs[tc*4];
    #pragma unroll
    for (int i = 0; i < 8; i++) {
        int gr = row0 + tr*8 + i;
        if (gr < M) {
            float v0, v1, v2, v3;
            unpk2(acc[i][0], v0, v1);
            unpk2(acc[i][1], v2, v3);
            float o0 = v0 + bsv.x, o1 = v1 + bsv.y, o2 = v2 + bsv.z, o3 = v3 + bsv.w;
            __nv_bfloat16 h0 = __float2bfloat16_rn(o0), h1 = __float2bfloat16_rn(o1);
            __nv_bfloat16 h2 = __float2bfloat16_rn(o2), h3 = __float2bfloat16_rn(o3);
            uint2 uh = make_uint2(
                ((uint32_t)__bfloat16_as_ushort(h1) << 16) | __bfloat16_as_ushort(h0),
                ((uint32_t)__bfloat16_as_ushort(h3) << 16) | __bfloat16_as_ushort(h2));
            uint2 ul = make_uint2(
                pkbf(o0 - __bfloat162float(h0), o1 - __bfloat162float(h1)),
                pkbf(o2 - __bfloat162float(h2), o3 - __bfloat162float(h3)));
            *(uint2*)&dst[(size_t)gr*256 + tc*4]       = uh;
            *(uint2*)&dst[(size_t)gr*256 + 128 + tc*4] = ul;
        }
    }
}

// ---------------- warp-MMA message-passing block kernel (single buffer, LDG+STS) ----------------
template<bool IS_EDGE>
__global__ void __launch_bounds__(THREADS, 1)
blk_mma_kernel(const float* __restrict__ b1, const float* __restrict__ b2, int blk) {
    extern __shared__ char smem[];
    float* b1s = (float*)(smem + MB_B1);
    float* b2s = (float*)(smem + MB_B2);
    int*   sSl = (int*)(smem + MB_SS);
    int*   sRl = (int*)(smem + MB_SR);

    const int M = IS_EDGE ? NE : NN;
    constexpr int KIN = IS_EDGE ? 384 : 256;
    constexpr int NS1 = KIN / 64;

    const __nv_bfloat16* w1h = IS_EDGE ? (g_wE1h + (size_t)blk * 128 * KIN)
                                       : (g_wN1h + (size_t)blk * 128 * KIN);
    const __nv_bfloat16* w1l = IS_EDGE ? (g_wE1l + (size_t)blk * 128 * KIN)
                                       : (g_wN1l + (size_t)blk * 128 * KIN);
    const __nv_bfloat16* w2h = IS_EDGE ? (g_wE2h + (size_t)blk * 128 * 128)
                                       : (g_wN2h + (size_t)blk * 128 * 128);
    const __nv_bfloat16* w2l = IS_EDGE ? (g_wE2l + (size_t)blk * 128 * 128)
                                       : (g_wN2l + (size_t)blk * 128 * 128);

    int tid = threadIdx.x;
    int wid = tid >> 5, lid = tid & 31;
    int wm = wid & 3, wn = wid >> 2;
    int row0 = blockIdx.x * BM;
    uint32_t sb = smem_u32(smem);

    if (tid < 128) {
        b1s[tid] = __ldg(&b1[tid]);
        b2s[tid] = __ldg(&b2[tid]);
        if (IS_EDGE) {
            int e = min(row0 + tid, NE - 1);
            sSl[tid] = g_send[e];
            sRl[tid] = g_recv[e];
        }
    }
    __syncthreads();

    // ===== stage 1: D1 = X @ W1 =====
    float acc[2][4][4];
    #pragma unroll
    for (int a = 0; a < 2; a++)
        #pragma unroll
        for (int b = 0; b < 4; b++)
            #pragma unroll
            for (int c = 0; c < 4; c++) acc[a][b][c] = 0.f;

    #pragma unroll 1
    for (int kt = 0; kt < NS1; kt++) {
        stage_slab<IS_EDGE>(smem, kt, row0, M, sSl, sRl, w1h, w1l, KIN, tid);
        __syncthreads();
        mma_slab(acc, sb, wm, wn, lid);
        __syncthreads();
    }

    // ===== stage 2: D2 = relu(D1 + b1) @ W2 =====
    float acc2[2][4][4];
    #pragma unroll
    for (int a = 0; a < 2; a++)
        #pragma unroll
        for (int b = 0; b < 4; b++)
            #pragma unroll
            for (int c = 0; c < 4; c++) acc2[a][b][c] = 0.f;

    #pragma unroll 1
    for (int s = 0; s < 2; s++) {
        if ((wn >> 1) == s) {
            #pragma unroll
            for (int ma = 0; ma < 2; ma++) {
                int rlo = wm*32 + ma*16 + (lid >> 2);
                #pragma unroll
                for (int na = 0; na < 4; na++) {
                    int col = wn*32 + na*8 + (lid & 3)*2;
                    uint32_t cb = (uint32_t)((col - s*64) * 2);
                    float x0 = fmaxf(acc[ma][na][0] + b1s[col],     0.f);
                    float x1 = fmaxf(acc[ma][na][1] + b1s[col + 1], 0.f);
                    __nv_bfloat16 hh0 = __float2bfloat16_rn(x0), hh1 = __float2bfloat16_rn(x1);
                    uint32_t o0 = swz((uint32_t)(rlo * 128) + cb);
                    *(uint32_t*)(smem + o0) =
                        ((uint32_t)__bfloat16_as_ushort(hh1) << 16) | __bfloat16_as_ushort(hh0);
                    *(uint32_t*)(smem + OFF_AL + o0) =
                        pkbf(x0 - __bfloat162float(hh0), x1 - __bfloat162float(hh1));
                    float x2 = fmaxf(acc[ma][na][2] + b1s[col],     0.f);
                    float x3 = fmaxf(acc[ma][na][3] + b1s[col + 1], 0.f);
                    __nv_bfloat16 hh2 = __float2bfloat16_rn(x2), hh3 = __float2bfloat16_rn(x3);
                    uint32_t o1 = swz((uint32_t)((rlo + 8) * 128) + cb);
                    *(uint32_t*)(smem + o1) =
                        ((uint32_t)__bfloat16_as_ushort(hh3) << 16) | __bfloat16_as_ushort(hh2);
                    *(uint32_t*)(smem + OFF_AL + o1) =
                        pkbf(x2 - __bfloat162float(hh2), x3 - __bfloat162float(hh3));
                }
            }
        }
        // W2 slab (LDG+STS)
        #pragma unroll
        for (int q = 0; q < 2; q++) {
            int f = tid + q * THREADS;
            int n = f >> 3, ch = f & 7;
            uint4 vh = __ldg((const uint4*)(w2h + (size_t)n * 128 + s*64 + ch * 8));
            uint4 vl = __ldg((const uint4*)(w2l + (size_t)n * 128 + s*64 + ch * 8));
            uint32_t o = OFF_BH + swz((uint32_t)(n * 128 + ch * 16));
            *(uint4*)(smem + o) = vh;
            *(uint4*)(smem + o + 16384) = vl;
        }
        __syncthreads();
        mma_slab(acc2, sb, wm, wn, lid);
        __syncthreads();
    }

    // node: zero this tile's g_agg rows for next iteration
    if (!IS_EDGE) {
        float4 z4 = make_float4(0.f, 0.f, 0.f, 0.f);
        #pragma unroll
        for (int q = 0; q < 8; q++) {
            int f = tid + q * THREADS;
            int rr = f >> 5, cc = (f & 31) << 2;
            int gr2 = row0 + rr;
            if (gr2 < NN) *(float4*)&g_agg[(size_t)gr2*HD + cc] = z4;
        }
    }

    // ===== epilogue: bias2 + residual (hi+lo) + split store (+ scatter-add) =====
    __nv_bfloat16* dst = IS_EDGE ? g_ef_s : g_nf_s;
    #pragma unroll
    for (int ma = 0; ma < 2; ma++) {
        int rlo = wm*32 + ma*16 + (lid >> 2);
        #pragma unroll
        for (int half = 0; half < 2; half++) {
            int r = rlo + half*8;
            int gr = row0 + r;
            if (gr < M) {
                int rv = IS_EDGE ? sRl[r] : 0;
                #pragma unroll
                for (int na = 0; na < 4; na++) {
                    int col = wn*32 + na*8 + (lid & 3)*2;
                    float v0 = acc2[ma][na][half*2]     + b2s[col];
                    float v1 = acc2[ma][na][half*2 + 1] + b2s[col + 1];
                    uint32_t hw = *(uint32_t*)&dst[(size_t)gr*256 + col];
                    uint32_t lw = *(uint32_t*)&dst[(size_t)gr*256 + 128 + col];
                    float2 hv = upbf2(hw), lv = upbf2(lw);
                    float n0 = v0 + hv.x + lv.x;
                    float n1 = v1 + hv.y + lv.y;
                    __nv_bfloat16 h0 = __float2bfloat16_rn(n0), h1 = __float2bfloat16_rn(n1);
                    *(uint32_t*)&dst[(size_t)gr*256 + col] =
                        ((uint32_t)__bfloat16_as_ushort(h1) << 16) | __bfloat16_as_ushort(h0);
                    *(uint32_t*)&dst[(size_t)gr*256 + 128 + col] =
                        pkbf(n0 - __bfloat162float(h0), n1 - __bfloat162float(h1));
                    if (IS_EDGE) {
                        float* ap = &g_agg[(size_t)rv*HD + col];
                        atomicAdd(ap,     n0);
                        atomicAdd(ap + 1, n1);
                    }
                }
            }
        }
    }
}

// ---------------- decoder (f32x2 path, split nf input) ----------------
__global__ void __launch_bounds__(THREADS, 1)
dec_kernel(const float* __restrict__ W1, const float* __restrict__ b1,
           const float* __restrict__ W2, const float* __restrict__ b2,
           const float* __restrict__ zl, const float* __restrict__ zt,
           float* __restrict__ out) {
    extern __shared__ float smf[];
    float* Hs  = smf + SM_HS;
    float* Ws  = smf + SM_WS;
    float* Xs  = smf + SM_XS;
    float* b1s = smf + SM_X3;
    __shared__ double sm[4][16];

    int tid = threadIdx.x;
    int tr = tid >> 5, tc = tid & 31;
    int row0 = blockIdx.x * BM;

    if (tid >= THREADS - BN) b1s[tid - (THREADS - BN)] = __ldg(&b1[tid - (THREADS - BN)]);
    __syncthreads();

    ull acc[8][2];
    #pragma unroll
    for (int i = 0; i < 8; i++) { acc[i][0] = 0ull; acc[i][1] = 0ull; }

    #pragma unroll 1
    for (int kt = 0; kt < 4; kt++) {
        load_W_tile(Ws, W1, kt, tid);
        #pragma unroll
        for (int q = 0; q < 2; q++) {
            int f = tid + q * THREADS;
            int rr = f >> 3, c4 = (f & 7) << 2;
            int gr = min(row0 + rr, NN - 1);
            int k = kt*BK + c4;
            uint2 hh = *(const uint2*)&g_nf_s[(size_t)gr*256 + k];
            uint2 ll = *(const uint2*)&g_nf_s[(size_t)gr*256 + 128 + k];
            float2 h0 = upbf2(hh.x), h1 = upbf2(hh.y);
            float2 l0 = upbf2(ll.x), l1 = upbf2(ll.y);
            *(float4*)&Xs[rr * XLD + c4] =
                make_float4(h0.x + l0.x, h0.y + l0.y, h1.x + l1.x, h1.y + l1.y);
        }
        __syncthreads();
        gemm84<XLD>(acc, Xs, Ws, tr, tc);
        __syncthreads();
    }
    float4 b1v = *(float4*)&b1s[tc*4];
    #pragma unroll
    for (int i = 0; i < 8; i++) {
        int r = tr*8 + i;
        float v0, v1, v2, v3;
        unpk2(acc[i][0], v0, v1);
        unpk2(acc[i][1], v2, v3);
        float4 h = make_float4(fmaxf(v0 + b1v.x, 0.f), fmaxf(v1 + b1v.y, 0.f),
                               fmaxf(v2 + b1v.z, 0.f), fmaxf(v3 + b1v.w, 0.f));
        *(float4*)&Hs[r*HLD + tc*4] = h;
    }
    for (int i = tid; i < 384; i += THREADS) Ws[i] = __ldg(&W2[i]);
    __syncthreads();

    double vls = 0.0, ve0 = 0.0, ve1 = 0.0, ve2 = 0.0;
    if (tid < BM) {
        int gr = row0 + tid;
        if (gr < NN) {
            float o0 = __ldg(&b2[0]), o1 = __ldg(&b2[1]), o2 = __ldg(&b2[2]);
            #pragma unroll 8
            for (int k = 0; k < HD; k += 4) {
                float4 h = *(const float4*)&Hs[tid*HLD + k];
                o0 += h.x*Ws[k*3+0] + h.y*Ws[(k+1)*3+0] + h.z*Ws[(k+2)*3+0] + h.w*Ws[(k+3)*3+0];
                o1 += h.x*Ws[k*3+1] + h.y*Ws[(k+1)*3+1] + h.z*Ws[(k+2)*3+1] + h.w*Ws[(k+3)*3+1];
                o2 += h.x*Ws[k*3+2] + h.y*Ws[(k+1)*3+2] + h.z*Ws[(k+2)*3+2] + h.w*Ws[(k+3)*3+2];
            }
            float om[3], os[3];
            #pragma unroll
            for (int k = 0; k < 3; k++) {
                double m = g_acc[12 + k] / NN, q = g_acc[15 + k] / NN;
                double sd = fmax(sqrt(fmax(q - m*m, 0.0)), 1e-8);
                om[k] = (float)m; os[k] = (float)sd;
            }
            float zl0 = zl[gr*3], zl1 = zl[gr*3+1], zl2 = zl[gr*3+2];
            float zt0 = zt[gr*3], zt1 = zt[gr*3+1], zt2 = zt[gr*3+2];
            float d0 = (zt0 - zl0 - om[0])/os[0] - o0;
            float d1 = (zt1 - zl1 - om[1])/os[1] - o1;
            float d2 = (zt2 - zl2 - om[2])/os[2] - o2;
            vls = (double)d0*d0 + (double)d1*d1 + (double)d2*d2;
            float zp0 = zl0 + o0*os[0] + om[0];
            float zp1 = zl1 + o1*os[1] + om[1];
            float zp2 = zl2 + o2*os[2] + om[2];
            out[gr*3]   = zp0;
            out[gr*3+1] = zp1;
            out[gr*3+2] = zp2;
            float e0 = zp0 - zt0, e1 = zp1 - zt1, e2 = zp2 - zt2;
            ve0 = (double)e0*e0; ve1 = (double)e1*e1; ve2 = (double)e2*e2;
        }
    }
    int w = tid >> 5, l = tid & 31;
    double r0 = wred(vls), r1 = wred(ve0), r2 = wred(ve1), r3 = wred(ve2);
    if (l == 0) { sm[0][w] = r0; sm[1][w] = r1; sm[2][w] = r2; sm[3][w] = r3; }
    __syncthreads();
    if (tid < 4) {
        double t = 0;
        #pragma unroll
        for (int j = 0; j < 16; j++) t += sm[tid][j];
        atomicAdd(&g_acc[18 + tid], t);
    }
}

// ---------------- finalize ----------------
__global__ void finalize_out_kernel(float* out, int out_size) {
    if (blockIdx.x == 0 && threadIdx.x == 0) {
        double loss = g_acc[18] / (3.0 * NN);
        double r = 0.0;
        for (int c = 0; c < 3; c++) r += sqrt(g_acc[19 + c] / NN);
        r /= 3.0;
        if (out_size >= NN*3 + 1) out[NN*3]     = (float)loss;
        if (out_size >= NN*3 + 2) out[NN*3 + 1] = (float)r;
    }
    for (int i = NN*3 + 2 + blockIdx.x * 256 + threadIdx.x; i < out_size; i += 32 * 256)
        out[i] = 0.f;
}

// ---------------- host launcher ----------------
extern "C" void kernel_launch(void* const* d_in, const int* in_sizes, int n_in,
                              void* d_out, int out_size) {
    if (n_in < 25 || d_out == nullptr) return;
    const float* z    = (const float*)d_in[0];
    const float* zt   = (const float*)d_in[1];
    const float* pos  = (const float*)d_in[2];
    const float* enW1 = (const float*)d_in[3];  const float* enb1 = (const float*)d_in[4];
    const float* enW2 = (const float*)d_in[5];  const float* enb2 = (const float*)d_in[6];
    const float* eeW1 = (const float*)d_in[7];  const float* eeb1 = (const float*)d_in[8];
    const float* eeW2 = (const float*)d_in[9];  const float* eeb2 = (const float*)d_in[10];
    const float* dW1  = (const float*)d_in[11]; const float* db1  = (const float*)d_in[12];
    const float* dW2  = (const float*)d_in[13]; const float* db2  = (const float*)d_in[14];
    const float* beW1 = (const float*)d_in[15]; const float* beb1 = (const float*)d_in[16];
    const float* beW2 = (const float*)d_in[17]; const float* beb2 = (const float*)d_in[18];
    const float* bnW1 = (const float*)d_in[19]; const float* bnb1 = (const float*)d_in[20];
    const float* bnW2 = (const float*)d_in[21]; const float* bnb2 = (const float*)d_in[22];
    const int* snd = (const int*)d_in[23];
    const int* rcv = (const int*)d_in[24];
    const float* zl = z + (size_t)(in_sizes[0] - NN * 3);
    float* out = (float*)d_out;

    cudaFuncSetAttribute(enc_kernel, cudaFuncAttributeMaxDynamicSharedMemorySize, SMEM_BYTES);
    cudaFuncSetAttribute(dec_kernel, cudaFuncAttributeMaxDynamicSharedMemorySize, SMEM_BYTES);
    cudaFuncSetAttribute(blk_mma_kernel<true>,  cudaFuncAttributeMaxDynamicSharedMemorySize, MMA_SMEM);
    cudaFuncSetAttribute(blk_mma_kernel<false>, cudaFuncAttributeMaxDynamicSharedMemorySize, MMA_SMEM);

    detect_idx_kernel<<<1, 256>>>(snd);
    prep_w_kernel<<<896, 512>>>(beW1, beW2, bnW1, bnW2);
    convert_idx_kernel<<<ESTAT, 256>>>(snd, rcv);
    stats_kernel<<<ESTAT + NSTAT, 256>>>(pos, zl, zt);
    enc_kernel<<<EBLK + NBLK, THREADS, SMEM_BYTES>>>(enW1, enb1, enW2, enb2,
                                                     eeW1, eeb1, eeW2, eeb2, zl);
    for (int b = 0; b < 4; b++) {
        blk_mma_kernel<true><<<EBLK, THREADS, MMA_SMEM>>>(beb1 + (size_t)b * HD,
                                                          beb2 + (size_t)b * HD, b);
        blk_mma_kernel<false><<<NBLK, THREADS, MMA_SMEM>>>(bnb1 + (size_t)b * HD,
                                                           bnb2 + (size_t)b * HD, b);
    }
    dec_kernel<<<NBLK, THREADS, SMEM_BYTES>>>(dW1, db1, dW2, db2, zl, zt, out);
    finalize_out_kernel<<<32, 256>>>(out, out_size);
}

// round 16
// speedup vs baseline: 1.6288x; 1.6288x over previous
#include <cuda_runtime.h>
#include <cuda_bf16.h>
#include <math.h>
#include <stdint.h>

#define NN 30000
#define NE 180000
#define HD 128

#define BM 128
#define BK 32
#define BN 128
#define XLD 36
#define HLD 132
#define THREADS 512

// ---- enc/dec shared memory layout (floats) ----
#define SM_HS   0
#define SM_WS   (SM_HS + BM*HLD)
#define SM_XS   (SM_WS + BN*BN)
#define SM_BS   (SM_XS + BM*XLD)
#define SM_X3   (SM_BS + BN)
#define SM_IDX  (SM_X3 + BM*4)
#define SMEM_FLOATS (SM_IDX + 2*BM)
#define SMEM_BYTES (SMEM_FLOATS * 4)

// ---- blk mma kernel smem layout (bytes) ----
#define MS_AH   0
#define MS_AL   16384
#define MS_BH   32768
#define MS_BL   49152
#define MS_B1   65536
#define MS_B2   66048
#define MS_SS   66560
#define MS_SR   67072
#define MMA_SMEM 67584

#define EBLK ((NE + BM - 1) / BM)   // 1407
#define NBLK ((NN + BM - 1) / BM)   // 235
#define ESTAT ((NE + 255) / 256)
#define NSTAT ((NN + 255) / 256)

typedef unsigned long long ull;

// ---------------- device scratch ----------------
__device__ float  g_ef[(size_t)NE * HD];
__device__ float  g_nf[(size_t)NN * HD];
__device__ float  g_agg[(size_t)NN * HD];
__device__ float  g_efraw[(size_t)NE * 3];
__device__ int    g_send[NE];
__device__ int    g_recv[NE];
__device__ double g_acc[32];
__device__ int    g_is64;

// pre-transposed bf16 hi/lo weights: layout [blk][n (128)][k]
__device__ __nv_bfloat16 g_wE1h[4*384*128], g_wE1l[4*384*128];
__device__ __nv_bfloat16 g_wE2h[4*128*128], g_wE2l[4*128*128];
__device__ __nv_bfloat16 g_wN1h[4*256*128], g_wN1l[4*256*128];
__device__ __nv_bfloat16 g_wN2h[4*128*128], g_wN2l[4*128*128];

// ---------------- f32x2 helpers ----------------
__device__ __forceinline__ ull pk2(float x, float y) {
    ull r; asm("mov.b64 %0, {%1, %2};" : "=l"(r) : "f"(x), "f"(y)); return r;
}
__device__ __forceinline__ void unpk2(ull v, float& x, float& y) {
    asm("mov.b64 {%0, %1}, %2;" : "=f"(x), "=f"(y) : "l"(v));
}
__device__ __forceinline__ ull fma2(ull a, ull b, ull c) {
    ull d; asm("fma.rn.f32x2 %0, %1, %2, %3;" : "=l"(d) : "l"(a), "l"(b), "l"(c)); return d;
}
__device__ __forceinline__ double wred(double v) {
    #pragma unroll
    for (int o = 16; o; o >>= 1) v += __shfl_down_sync(0xffffffffu, v, o);
    return v;
}

// ---------------- warp-mma helpers ----------------
__device__ __forceinline__ uint32_t smem_u32(const void* p) {
    uint32_t a;
    asm("{ .reg .u64 t; cvta.to.shared.u64 t, %1; cvt.u32.u64 %0, t; }" : "=r"(a) : "l"(p));
    return a;
}
__device__ __forceinline__ void ldsm4(uint32_t r[4], uint32_t addr) {
    asm volatile("ldmatrix.sync.aligned.m8n8.x4.shared.b16 {%0,%1,%2,%3}, [%4];"
        : "=r"(r[0]), "=r"(r[1]), "=r"(r[2]), "=r"(r[3]) : "r"(addr));
}
__device__ __forceinline__ void mma16816(float c[4], const uint32_t a[4], uint32_t b0, uint32_t b1) {
    asm volatile("mma.sync.aligned.m16n8k16.row.col.f32.bf16.bf16.f32 "
        "{%0,%1,%2,%3}, {%4,%5,%6,%7}, {%8,%9}, {%0,%1,%2,%3};"
        : "+f"(c[0]), "+f"(c[1]), "+f"(c[2]), "+f"(c[3])
        : "r"(a[0]), "r"(a[1]), "r"(a[2]), "r"(a[3]), "r"(b0), "r"(b1));
}
__device__ __forceinline__ uint32_t swz(uint32_t o) { return o ^ ((o >> 3) & 0x70); }
__device__ __forceinline__ uint32_t pkbf(float a, float b) {
    __nv_bfloat162 t = __floats2bfloat162_rn(a, b);
    return *(uint32_t*)&t;
}

// one 64-k slab of MMA over AH/AL vs BH/BL (hi*hi + hi*lo + lo*hi)
__device__ __forceinline__ void mma_slab(float acc[2][4][4], uint32_t abase,
                                         int wm, int wn, int lid) {
    #pragma unroll
    for (int k16 = 0; k16 < 4; k16++) {
        int kbA = k16*32 + ((lid >> 4) << 4);
        int rA  = lid & 15;
        uint32_t a0 = abase + swz((uint32_t)((wm*32 + rA)*128 + kbA));
        uint32_t a1 = abase + swz((uint32_t)((wm*32 + 16 + rA)*128 + kbA));
        uint32_t ah0[4], ah1[4], al0[4], al1[4];
        ldsm4(ah0, a0);           ldsm4(ah1, a1);
        ldsm4(al0, a0 + MS_AL);   ldsm4(al1, a1 + MS_AL);

        int g   = lid >> 3;
        int rB  = wn*32 + ((g >> 1) << 3) + (lid & 7);
        int kbB = k16*32 + ((g & 1) << 4);
        uint32_t b01 = abase + MS_BH + swz((uint32_t)(rB*128 + kbB));
        uint32_t b23 = abase + MS_BH + swz((uint32_t)((rB + 16)*128 + kbB));
        uint32_t bh01[4], bh23[4], bl01[4], bl23[4];
        ldsm4(bh01, b01);           ldsm4(bh23, b23);
        ldsm4(bl01, b01 + 16384);   ldsm4(bl23, b23 + 16384);

        #pragma unroll
        for (int ma = 0; ma < 2; ma++) {
            const uint32_t* ah = ma ? ah1 : ah0;
            const uint32_t* al = ma ? al1 : al0;
            mma16816(acc[ma][0], ah, bh01[0], bh01[1]);
            mma16816(acc[ma][0], ah, bl01[0], bl01[1]);
            mma16816(acc[ma][0], al, bh01[0], bh01[1]);
            mma16816(acc[ma][1], ah, bh01[2], bh01[3]);
            mma16816(acc[ma][1], ah, bl01[2], bl01[3]);
            mma16816(acc[ma][1], al, bh01[2], bh01[3]);
            mma16816(acc[ma][2], ah, bh23[0], bh23[1]);
            mma16816(acc[ma][2], ah, bl23[0], bl23[1]);
            mma16816(acc[ma][2], al, bh23[0], bh23[1]);
            mma16816(acc[ma][3], ah, bh23[2], bh23[3]);
            mma16816(acc[ma][3], ah, bl23[2], bl23[3]);
            mma16816(acc[ma][3], al, bh23[2], bh23[3]);
        }
    }
}

// LDG phase of slab staging (A fp32 gather + W bf16), results in registers
template<bool IS_EDGE>
__device__ __forceinline__ void ldg_slab(float4 pa[4], uint4 pbh[2], uint4 pbl[2],
                                         int kt, int row0, int M,
                                         const int* sSl, const int* sRl,
                                         const __nv_bfloat16* w1h, const __nv_bfloat16* w1l,
                                         int KIN, int tid) {
    int kbase = kt * 64;
    #pragma unroll
    for (int q = 0; q < 4; q++) {
        int f = tid + q * THREADS;        // 0..2047
        int rr = f >> 4;                  // row 0..127
        int c4 = (f & 15) << 2;           // k (floats) 0..60
        int gr = min(row0 + rr, M - 1);
        int k = kbase + c4;
        const float* sp;
        if (IS_EDGE) {
            if (k < 128)      sp = &g_ef[(size_t)gr*HD + k];
            else if (k < 256) sp = &g_nf[(size_t)sSl[rr]*HD + (k - 128)];
            else              sp = &g_nf[(size_t)sRl[rr]*HD + (k - 256)];
        } else {
            sp = (k < 128) ? &g_nf[(size_t)gr*HD + k] : &g_agg[(size_t)gr*HD + (k - 128)];
        }
        pa[q] = *(const float4*)sp;
    }
    #pragma unroll
    for (int q = 0; q < 2; q++) {
        int f = tid + q * THREADS;        // 0..1023
        int n = f >> 3, ch = f & 7;
        pbh[q] = __ldg((const uint4*)(w1h + (size_t)n * KIN + kbase + ch * 8));
        pbl[q] = __ldg((const uint4*)(w1l + (size_t)n * KIN + kbase + ch * 8));
    }
}

// STS phase: convert A fp32 -> bf16 hi/lo, store A + W into smem
__device__ __forceinline__ void sts_slab(const float4 pa[4], const uint4 pbh[2], const uint4 pbl[2],
                                         char* smem, int tid) {
    #pragma unroll
    for (int q = 0; q < 4; q++) {
        int f = tid + q * THREADS;
        int rr = f >> 4, c4 = (f & 15) << 2;
        float4 v = pa[q];
        __nv_bfloat16 h0 = __float2bfloat16_rn(v.x), h1 = __float2bfloat16_rn(v.y);
        __nv_bfloat16 h2 = __float2bfloat16_rn(v.z), h3 = __float2bfloat16_rn(v.w);
        uint32_t h01 = ((uint32_t)__bfloat16_as_ushort(h1) << 16) | __bfloat16_as_ushort(h0);
        uint32_t h23 = ((uint32_t)__bfloat16_as_ushort(h3) << 16) | __bfloat16_as_ushort(h2);
        uint32_t l01 = pkbf(v.x - __bfloat162float(h0), v.y - __bfloat162float(h1));
        uint32_t l23 = pkbf(v.z - __bfloat162float(h2), v.w - __bfloat162float(h3));
        uint32_t o = swz((uint32_t)(rr * 128 + c4 * 2));
        *(uint2*)(smem + MS_AH + o) = make_uint2(h01, h23);
        *(uint2*)(smem + MS_AL + o) = make_uint2(l01, l23);
    }
    #pragma unroll
    for (int q = 0; q < 2; q++) {
        int f = tid + q * THREADS;
        int n = f >> 3, ch = f & 7;
        uint32_t o = swz((uint32_t)(n * 128 + ch * 16));
        *(uint4*)(smem + MS_BH + o) = pbh[q];
        *(uint4*)(smem + MS_BL + o) = pbl[q];
    }
}

// ---------------- launch 1: detect idx dtype + zero g_acc ----------------
__global__ void detect_idx_kernel(const int* __restrict__ s) {
    __shared__ int red;
    int tid = threadIdx.x;
    if (tid < 32) g_acc[tid] = 0.0;
    if (tid == 0) red = 0;
    __syncthreads();
    int any = 0;
    for (int i = tid; i < 8192; i += 256) any |= s[2*i + 1];
    if (any) atomicOr(&red, 1);
    __syncthreads();
    if (tid == 0) g_is64 = red ? 0 : 1;
}

// ---------------- weight transpose + bf16 hi/lo split ----------------
__global__ void prep_w_kernel(const float* __restrict__ eW1, const float* __restrict__ eW2,
                              const float* __restrict__ nW1, const float* __restrict__ nW2) {
    int i = blockIdx.x * 512 + threadIdx.x;   // [0, 458752)
    float v; __nv_bfloat16* dh; __nv_bfloat16* dl; int di;
    if (i < 196608) {                         // edge W1: [4][384][128]
        int b = i / 49152, j = i % 49152, k = j >> 7, n = j & 127;
        v = eW1[i]; di = b*49152 + n*384 + k; dh = g_wE1h; dl = g_wE1l;
    } else if (i < 262144) {                  // edge W2: [4][128][128]
        int j = (i - 196608), b = j / 16384; j %= 16384;
        int k = j >> 7, n = j & 127;
        v = eW2[i - 196608]; di = b*16384 + n*128 + k; dh = g_wE2h; dl = g_wE2l;
    } else if (i < 393216) {                  // node W1: [4][256][128]
        int j = (i - 262144), b = j / 32768; j %= 32768;
        int k = j >> 7, n = j & 127;
        v = nW1[i - 262144]; di = b*32768 + n*256 + k; dh = g_wN1h; dl = g_wN1l;
    } else {                                  // node W2
        int j = (i - 393216), b = j / 16384; j %= 16384;
        int k = j >> 7, n = j & 127;
        v = nW2[i - 393216]; di = b*16384 + n*128 + k; dh = g_wN2h; dl = g_wN2l;
    }
    __nv_bfloat16 h = __float2bfloat16_rn(v);
    dh[di] = h;
    dl[di] = __float2bfloat16_rn(v - __bfloat162float(h));
}

// ---------------- convert idx + zero g_agg ----------------
__global__ void convert_idx_kernel(const int* __restrict__ s, const int* __restrict__ r) {
    int i = blockIdx.x * 256 + threadIdx.x;
    if (i < NE) {
        int w = g_is64 ? 2*i : i;
        g_send[i] = min(max(s[w], 0), NN - 1);
        g_recv[i] = min(max(r[w], 0), NN - 1);
    }
    const int total4 = NN * HD / 4;
    float4 z4 = make_float4(0.f, 0.f, 0.f, 0.f);
    for (int j = blockIdx.x * 256 + threadIdx.x; j < total4; j += ESTAT * 256)
        ((float4*)g_agg)[j] = z4;
}

// ---------------- fused edge+node stats ----------------
__global__ void stats_kernel(const float* __restrict__ pos, const float* __restrict__ zl,
                             const float* __restrict__ zt) {
    __shared__ double sm[12][8];
    int tid = threadIdx.x, w = tid >> 5, l = tid & 31;
    int b = blockIdx.x;
    if (b < ESTAT) {
        int e = b * 256 + tid;
        double v[6] = {0, 0, 0, 0, 0, 0};
        if (e < NE) {
            int s = g_send[e], r = g_recv[e];
            float rx = pos[2*s]   - pos[2*r];
            float ry = pos[2*s+1] - pos[2*r+1];
            float nn = sqrtf(rx*rx + ry*ry);
            g_efraw[3*e] = rx; g_efraw[3*e+1] = ry; g_efraw[3*e+2] = nn;
            v[0] = rx; v[1] = ry; v[2] = nn;
            v[3] = (double)rx*rx; v[4] = (double)ry*ry; v[5] = (double)nn*nn;
        }
        #pragma unroll
        for (int i = 0; i < 6; i++) { double rv = wred(v[i]); if (l == 0) sm[i][w] = rv; }
        __syncthreads();
        if (tid < 6) {
            double t = 0;
            #pragma unroll
            for (int j = 0; j < 8; j++) t += sm[tid][j];
            atomicAdd(&g_acc[tid], t);
        }
    } else {
        int n = (b - ESTAT) * 256 + tid;
        double v[12];
        #pragma unroll
        for (int i = 0; i < 12; i++) v[i] = 0;
        if (n < NN) {
            #pragma unroll
            for (int c = 0; c < 3; c++) {
                float a = zl[n*3 + c];
                float t = zt[n*3 + c] - a;
                v[c] = a; v[3+c] = (double)a*a; v[6+c] = t; v[9+c] = (double)t*t;
            }
        }
        #pragma unroll
        for (int i = 0; i < 12; i++) { double rv = wred(v[i]); if (l == 0) sm[i][w] = rv; }
        __syncthreads();
        if (tid < 12) {
            double t = 0;
            #pragma unroll
            for (int j = 0; j < 8; j++) t += sm[tid][j];
            atomicAdd(&g_acc[6 + tid], t);
        }
    }
}

// ---------------- f32x2 GEMM inner (enc/dec) ----------------
template<int LDA>
__device__ __forceinline__ void gemm84(ull acc[8][2], const float* __restrict__ A,
                                       const float* __restrict__ Ws, int tr, int tc) {
    #pragma unroll
    for (int k4 = 0; k4 < BK; k4 += 4) {
        float4 af[8];
        #pragma unroll
        for (int i = 0; i < 8; i++)
            af[i] = *(const float4*)&A[(tr*8 + i) * LDA + k4];
        #pragma unroll
        for (int s = 0; s < 4; s++) {
            float4 b = *(const float4*)&Ws[(k4 + s) * BN + tc*4];
            ull bp0 = pk2(b.x, b.y), bp1 = pk2(b.z, b.w);
            #pragma unroll
            for (int i = 0; i < 8; i++) {
                float av = (s == 0) ? af[i].x : (s == 1) ? af[i].y : (s == 2) ? af[i].z : af[i].w;
                ull a2 = pk2(av, av);
                acc[i][0] = fma2(a2, bp0, acc[i][0]);
                acc[i][1] = fma2(a2, bp1, acc[i][1]);
            }
        }
    }
}

__device__ __forceinline__ void load_W_tile(float* Ws, const float* __restrict__ W, int kt, int tid) {
    const float* wp = W + (size_t)kt * BK * BN;
    #pragma unroll
    for (int q = 0; q < 2; q++) {
        int f = tid + q * THREADS;
        int rr = f >> 5, cc = (f & 31) << 2;
        *(float4*)&Ws[rr * BN + cc] = __ldg((const float4*)&wp[rr * BN + cc]);
    }
}

__device__ __forceinline__ void load_W_full(float* Ws, const float* __restrict__ W, int tid) {
    #pragma unroll
    for (int q = 0; q < 8; q++) {
        int f = tid + q * THREADS;
        int rr = f >> 5, cc = (f & 31) << 2;
        *(float4*)&Ws[rr * BN + cc] = __ldg((const float4*)&W[rr * BN + cc]);
    }
}

// ---------------- fused encoders (f32x2 path) ----------------
__global__ void __launch_bounds__(THREADS, 1)
enc_kernel(const float* __restrict__ enW1, const float* __restrict__ enb1,
           const float* __restrict__ enW2, const float* __restrict__ enb2,
           const float* __restrict__ eeW1, const float* __restrict__ eeb1,
           const float* __restrict__ eeW2, const float* __restrict__ eeb2,
           const float* __restrict__ zl) {
    extern __shared__ float smf[];
    float* Hs  = smf + SM_HS;
    float* Ws  = smf + SM_WS;
    float* bs  = smf + SM_BS;
    float* x3  = smf + SM_X3;
    float* w1s = smf + SM_XS;
    float* b1s = w1s + 384;

    bool isEdge = blockIdx.x < EBLK;
    int  row0   = (isEdge ? blockIdx.x : blockIdx.x - EBLK) * BM;
    int  M      = isEdge ? NE : NN;
    const float* W1 = isEdge ? eeW1 : enW1;
    const float* b1 = isEdge ? eeb1 : enb1;
    const float* W2 = isEdge ? eeW2 : enW2;
    const float* b2 = isEdge ? eeb2 : enb2;

    int tid = threadIdx.x;
    int tr = tid >> 5, tc = tid & 31;

    if (tid < 3 * BN) w1s[tid] = __ldg(&W1[tid]);
    else if (tid < 4 * BN) b1s[tid - 3*BN] = __ldg(&b1[tid - 3*BN]);
    if (tid < BN) bs[tid] = __ldg(&b2[tid]);
    if (tid >= THREADS - BM) {
        int t = tid - (THREADS - BM);
        int r = min(row0 + t, M - 1);
        int base = isEdge ? 0 : 6;
        double cnt = isEdge ? (double)NE : (double)NN;
        const float* src = isEdge ? (g_efraw + (size_t)3*r) : (zl + (size_t)3*r);
        #pragma unroll
        for (int k = 0; k < 3; k++) {
            double m = g_acc[base + k] / cnt, q = g_acc[base + 3 + k] / cnt;
            double sd = fmax(sqrt(fmax(q - m*m, 0.0)), 1e-8);
            x3[t*4 + k] = (src[k] - (float)m) / (float)sd;
        }
    }
    load_W_full(Ws, W2, tid);
    __syncthreads();

    #pragma unroll
    for (int i = 0; i < 8; i++) {
        int r = tr*8 + i;
        float x0 = x3[r*4], x1 = x3[r*4+1], x2 = x3[r*4+2];
        float4 h;
        float* hp = &h.x;
        #pragma unroll
        for (int j = 0; j < 4; j++) {
            int c = tc*4 + j;
            hp[j] = fmaxf(b1s[c] + x0*w1s[c] + x1*w1s[BN + c] + x2*w1s[2*BN + c], 0.f);
        }
        *(float4*)&Hs[r*HLD + tc*4] = h;
    }
    __syncthreads();

    ull acc[8][2];
    #pragma unroll
    for (int i = 0; i < 8; i++) { acc[i][0] = 0ull; acc[i][1] = 0ull; }
    #pragma unroll
    for (int kt = 0; kt < 4; kt++)
        gemm84<HLD>(acc, Hs + kt * BK, Ws + kt * BK * BN, tr, tc);

    float* dst = isEdge ? g_ef : g_nf;
    float4 bsv = *(float4*)&bs[tc*4];
    #pragma unroll
    for (int i = 0; i < 8; i++) {
        int gr = row0 + tr*8 + i;
        if (gr < M) {
            float v0, v1, v2, v3;
            unpk2(acc[i][0], v0, v1);
            unpk2(acc[i][1], v2, v3);
            float4 o = make_float4(v0 + bsv.x, v1 + bsv.y, v2 + bsv.z, v3 + bsv.w);
            *(float4*)&dst[(size_t)gr*HD + tc*4] = o;
        }
    }
}

// ---------------- warp-MMA message-passing block kernel (register-prefetch pipeline) ----------------
template<bool IS_EDGE>
__global__ void __launch_bounds__(THREADS, 1)
blk_mma_kernel(const float* __restrict__ b1, const float* __restrict__ b2, int blk) {
    extern __shared__ char smem[];
    float* b1s = (float*)(smem + MS_B1);
    float* b2s = (float*)(smem + MS_B2);
    int*   sSl = (int*)(smem + MS_SS);
    int*   sRl = (int*)(smem + MS_SR);

    const int M = IS_EDGE ? NE : NN;
    constexpr int KIN = IS_EDGE ? 384 : 256;
    constexpr int NS1 = KIN / 64;

    const __nv_bfloat16* w1h = IS_EDGE ? (g_wE1h + (size_t)blk * 128 * KIN)
                                       : (g_wN1h + (size_t)blk * 128 * KIN);
    const __nv_bfloat16* w1l = IS_EDGE ? (g_wE1l + (size_t)blk * 128 * KIN)
                                       : (g_wN1l + (size_t)blk * 128 * KIN);
    const __nv_bfloat16* w2h = IS_EDGE ? (g_wE2h + (size_t)blk * 128 * 128)
                                       : (g_wN2h + (size_t)blk * 128 * 128);
    const __nv_bfloat16* w2l = IS_EDGE ? (g_wE2l + (size_t)blk * 128 * 128)
                                       : (g_wN2l + (size_t)blk * 128 * 128);

    int tid = threadIdx.x;
    int wid = tid >> 5, lid = tid & 31;
    int wm = wid & 3, wn = wid >> 2;
    int row0 = blockIdx.x * BM;
    uint32_t sb = smem_u32(smem);

    if (tid < 128) {
        b1s[tid] = __ldg(&b1[tid]);
        b2s[tid] = __ldg(&b2[tid]);
        if (IS_EDGE) {
            int e = min(row0 + tid, NE - 1);
            sSl[tid] = g_send[e];
            sRl[tid] = g_recv[e];
        }
    }
    __syncthreads();

    // ===== stage 1: D1 = X @ W1 (register-prefetch pipeline) =====
    float acc[2][4][4];
    #pragma unroll
    for (int a = 0; a < 2; a++)
        #pragma unroll
        for (int b = 0; b < 4; b++)
            #pragma unroll
            for (int c = 0; c < 4; c++) acc[a][b][c] = 0.f;

    float4 pa[4];
    uint4  pbh[2], pbl[2];
    ldg_slab<IS_EDGE>(pa, pbh, pbl, 0, row0, M, sSl, sRl, w1h, w1l, KIN, tid);
    #pragma unroll 1
    for (int kt = 0; kt < NS1; kt++) {
        sts_slab(pa, pbh, pbl, smem, tid);
        if (kt + 1 < NS1)
            ldg_slab<IS_EDGE>(pa, pbh, pbl, kt + 1, row0, M, sSl, sRl, w1h, w1l, KIN, tid);
        __syncthreads();
        mma_slab(acc, sb, wm, wn, lid);
        __syncthreads();
    }

    // ===== stage 2: D2 = relu(D1 + b1) @ W2 =====
    float acc2[2][4][4];
    #pragma unroll
    for (int a = 0; a < 2; a++)
        #pragma unroll
        for (int b = 0; b < 4; b++)
            #pragma unroll
            for (int c = 0; c < 4; c++) acc2[a][b][c] = 0.f;

    #pragma unroll 1
    for (int s = 0; s < 2; s++) {
        if ((wn >> 1) == s) {
            #pragma unroll
            for (int ma = 0; ma < 2; ma++) {
                int rlo = wm*32 + ma*16 + (lid >> 2);
                #pragma unroll
                for (int na = 0; na < 4; na++) {
                    int col = wn*32 + na*8 + (lid & 3)*2;
                    uint32_t cb = (uint32_t)((col - s*64) * 2);
                    float x0 = fmaxf(acc[ma][na][0] + b1s[col],     0.f);
                    float x1 = fmaxf(acc[ma][na][1] + b1s[col + 1], 0.f);
                    __nv_bfloat16 hh0 = __float2bfloat16_rn(x0), hh1 = __float2bfloat16_rn(x1);
                    uint32_t o0 = swz((uint32_t)(rlo * 128) + cb);
                    *(uint32_t*)(smem + o0) =
                        ((uint32_t)__bfloat16_as_ushort(hh1) << 16) | __bfloat16_as_ushort(hh0);
                    *(uint32_t*)(smem + MS_AL + o0) =
                        pkbf(x0 - __bfloat162float(hh0), x1 - __bfloat162float(hh1));
                    float x2 = fmaxf(acc[ma][na][2] + b1s[col],     0.f);
                    float x3 = fmaxf(acc[ma][na][3] + b1s[col + 1], 0.f);
                    __nv_bfloat16 hh2 = __float2bfloat16_rn(x2), hh3 = __float2bfloat16_rn(x3);
                    uint32_t o1 = swz((uint32_t)((rlo + 8) * 128) + cb);
                    *(uint32_t*)(smem + o1) =
                        ((uint32_t)__bfloat16_as_ushort(hh3) << 16) | __bfloat16_as_ushort(hh2);
                    *(uint32_t*)(smem + MS_AL + o1) =
                        pkbf(x2 - __bfloat162float(hh2), x3 - __bfloat162float(hh3));
                }
            }
        }
        // W2 slab: k range [s*64, s*64+64)
        #pragma unroll
        for (int q = 0; q < 2; q++) {
            int f = tid + q * THREADS;
            int n = f >> 3, ch = f & 7;
            uint4 vh = __ldg((const uint4*)(w2h + (size_t)n * 128 + s*64 + ch * 8));
            uint4 vl = __ldg((const uint4*)(w2l + (size_t)n * 128 + s*64 + ch * 8));
            uint32_t o = swz((uint32_t)(n * 128 + ch * 16));
            *(uint4*)(smem + MS_BH + o) = vh;
            *(uint4*)(smem + MS_BL + o) = vl;
        }
        __syncthreads();
        mma_slab(acc2, sb, wm, wn, lid);
        __syncthreads();
    }

    // node: zero this tile's g_agg rows for next iteration (reads all done in stage 1)
    if (!IS_EDGE) {
        float4 z4 = make_float4(0.f, 0.f, 0.f, 0.f);
        #pragma unroll
        for (int q = 0; q < 8; q++) {
            int f = tid + q * THREADS;        // 0..4095
            int rr = f >> 5, cc = (f & 31) << 2;
            int gr2 = row0 + rr;
            if (gr2 < NN) *(float4*)&g_agg[(size_t)gr2*HD + cc] = z4;
        }
    }

    // ===== epilogue: bias2 + residual + store (+ scatter-add for edges) =====
    #pragma unroll
    for (int ma = 0; ma < 2; ma++) {
        int rlo = wm*32 + ma*16 + (lid >> 2);
        #pragma unroll
        for (int half = 0; half < 2; half++) {
            int r = rlo + half*8;
            int gr = row0 + r;
            if (gr < M) {
                int rv = IS_EDGE ? sRl[r] : 0;
                #pragma unroll
                for (int na = 0; na < 4; na++) {
                    int col = wn*32 + na*8 + (lid & 3)*2;
                    float v0 = acc2[ma][na][half*2]     + b2s[col];
                    float v1 = acc2[ma][na][half*2 + 1] + b2s[col + 1];
                    if (IS_EDGE) {
                        float2 prev = *(const float2*)&g_ef[(size_t)gr*HD + col];
                        float n0 = v0 + prev.x, n1 = v1 + prev.y;
                        *(float2*)&g_ef[(size_t)gr*HD + col] = make_float2(n0, n1);
                        float* ap = &g_agg[(size_t)rv*HD + col];
                        atomicAdd(ap,     n0);
                        atomicAdd(ap + 1, n1);
                    } else {
                        float2 prev = *(const float2*)&g_nf[(size_t)gr*HD + col];
                        *(float2*)&g_nf[(size_t)gr*HD + col] =
                            make_float2(v0 + prev.x, v1 + prev.y);
                    }
                }
            }
        }
    }
}

// ---------------- decoder (f32x2 path) ----------------
__global__ void __launch_bounds__(THREADS, 1)
dec_kernel(const float* __restrict__ W1, const float* __restrict__ b1,
           const float* __restrict__ W2, const float* __restrict__ b2,
           const float* __restrict__ zl, const float* __restrict__ zt,
           float* __restrict__ out) {
    extern __shared__ float smf[];
    float* Hs  = smf + SM_HS;
    float* Ws  = smf + SM_WS;
    float* Xs  = smf + SM_XS;
    float* b1s = smf + SM_X3;
    __shared__ double sm[4][16];

    int tid = threadIdx.x;
    int tr = tid >> 5, tc = tid & 31;
    int row0 = blockIdx.x * BM;

    if (tid >= THREADS - BN) b1s[tid - (THREADS - BN)] = __ldg(&b1[tid - (THREADS - BN)]);
    __syncthreads();

    ull acc[8][2];
    #pragma unroll
    for (int i = 0; i < 8; i++) { acc[i][0] = 0ull; acc[i][1] = 0ull; }

    #pragma unroll 1
    for (int kt = 0; kt < 4; kt++) {
        load_W_tile(Ws, W1, kt, tid);
        #pragma unroll
        for (int q = 0; q < 2; q++) {
            int f = tid + q * THREADS;
            int rr = f >> 3, c4 = (f & 7) << 2;
            int gr = min(row0 + rr, NN - 1);
            *(float4*)&Xs[rr * XLD + c4] =
                *(const float4*)&g_nf[(size_t)gr*HD + kt*BK + c4];
        }
        __syncthreads();
        gemm84<XLD>(acc, Xs, Ws, tr, tc);
        __syncthreads();
    }
    float4 b1v = *(float4*)&b1s[tc*4];
    #pragma unroll
    for (int i = 0; i < 8; i++) {
        int r = tr*8 + i;
        float v0, v1, v2, v3;
        unpk2(acc[i][0], v0, v1);
        unpk2(acc[i][1], v2, v3);
        float4 h = make_float4(fmaxf(v0 + b1v.x, 0.f), fmaxf(v1 + b1v.y, 0.f),
                               fmaxf(v2 + b1v.z, 0.f), fmaxf(v3 + b1v.w, 0.f));
        *(float4*)&Hs[r*HLD + tc*4] = h;
    }
    for (int i = tid; i < 384; i += THREADS) Ws[i] = __ldg(&W2[i]);
    __syncthreads();

    double vls = 0.0, ve0 = 0.0, ve1 = 0.0, ve2 = 0.0;
    if (tid < BM) {
        int gr = row0 + tid;
        if (gr < NN) {
            float o0 = __ldg(&b2[0]), o1 = __ldg(&b2[1]), o2 = __ldg(&b2[2]);
            #pragma unroll 8
            for (int k = 0; k < HD; k += 4) {
                float4 h = *(const float4*)&Hs[tid*HLD + k];
                o0 += h.x*Ws[k*3+0] + h.y*Ws[(k+1)*3+0] + h.z*Ws[(k+2)*3+0] + h.w*Ws[(k+3)*3+0];
                o1 += h.x*Ws[k*3+1] + h.y*Ws[(k+1)*3+1] + h.z*Ws[(k+2)*3+1] + h.w*Ws[(k+3)*3+1];
                o2 += h.x*Ws[k*3+2] + h.y*Ws[(k+1)*3+2] + h.z*Ws[(k+2)*3+2] + h.w*Ws[(k+3)*3+2];
            }
            float om[3], os[3];
            #pragma unroll
            for (int k = 0; k < 3; k++) {
                double m = g_acc[12 + k] / NN, q = g_acc[15 + k] / NN;
                double sd = fmax(sqrt(fmax(q - m*m, 0.0)), 1e-8);
                om[k] = (float)m; os[k] = (float)sd;
            }
            float zl0 = zl[gr*3], zl1 = zl[gr*3+1], zl2 = zl[gr*3+2];
            float zt0 = zt[gr*3], zt1 = zt[gr*3+1], zt2 = zt[gr*3+2];
            float d0 = (zt0 - zl0 - om[0])/os[0] - o0;
            float d1 = (zt1 - zl1 - om[1])/os[1] - o1;
            float d2 = (zt2 - zl2 - om[2])/os[2] - o2;
            vls = (double)d0*d0 + (double)d1*d1 + (double)d2*d2;
            float zp0 = zl0 + o0*os[0] + om[0];
            float zp1 = zl1 + o1*os[1] + om[1];
            float zp2 = zl2 + o2*os[2] + om[2];
            out[gr*3]   = zp0;
            out[gr*3+1] = zp1;
            out[gr*3+2] = zp2;
            float e0 = zp0 - zt0, e1 = zp1 - zt1, e2 = zp2 - zt2;
            ve0 = (double)e0*e0; ve1 = (double)e1*e1; ve2 = (double)e2*e2;
        }
    }
    int w = tid >> 5, l = tid & 31;
    double r0 = wred(vls), r1 = wred(ve0), r2 = wred(ve1), r3 = wred(ve2);
    if (l == 0) { sm[0][w] = r0; sm[1][w] = r1; sm[2][w] = r2; sm[3][w] = r3; }
    __syncthreads();
    if (tid < 4) {
        double t = 0;
        #pragma unroll
        for (int j = 0; j < 16; j++) t += sm[tid][j];
        atomicAdd(&g_acc[18 + tid], t);
    }
}

// ---------------- finalize ----------------
__global__ void finalize_out_kernel(float* out, int out_size) {
    if (blockIdx.x == 0 && threadIdx.x == 0) {
        double loss = g_acc[18] / (3.0 * NN);
        double r = 0.0;
        for (int c = 0; c < 3; c++) r += sqrt(g_acc[19 + c] / NN);
        r /= 3.0;
        if (out_size >= NN*3 + 1) out[NN*3]     = (float)loss;
        if (out_size >= NN*3 + 2) out[NN*3 + 1] = (float)r;
    }
    for (int i = NN*3 + 2 + blockIdx.x * 256 + threadIdx.x; i < out_size; i += 32 * 256)
        out[i] = 0.f;
}

// ---------------- host launcher ----------------
extern "C" void kernel_launch(void* const* d_in, const int* in_sizes, int n_in,
                              void* d_out, int out_size) {
    if (n_in < 25 || d_out == nullptr) return;
    const float* z    = (const float*)d_in[0];
    const float* zt   = (const float*)d_in[1];
    const float* pos  = (const float*)d_in[2];
    const float* enW1 = (const float*)d_in[3];  const float* enb1 = (const float*)d_in[4];
    const float* enW2 = (const float*)d_in[5];  const float* enb2 = (const float*)d_in[6];
    const float* eeW1 = (const float*)d_in[7];  const float* eeb1 = (const float*)d_in[8];
    const float* eeW2 = (const float*)d_in[9];  const float* eeb2 = (const float*)d_in[10];
    const float* dW1  = (const float*)d_in[11]; const float* db1  = (const float*)d_in[12];
    const float* dW2  = (const float*)d_in[13]; const float* db2  = (const float*)d_in[14];
    const float* beW1 = (const float*)d_in[15]; const float* beb1 = (const float*)d_in[16];
    const float* beW2 = (const float*)d_in[17]; const float* beb2 = (const float*)d_in[18];
    const float* bnW1 = (const float*)d_in[19]; const float* bnb1 = (const float*)d_in[20];
    const float* bnW2 = (const float*)d_in[21]; const float* bnb2 = (const float*)d_in[22];
    const int* snd = (const int*)d_in[23];
    const int* rcv = (const int*)d_in[24];
    const float* zl = z + (size_t)(in_sizes[0] - NN * 3);
    float* out = (float*)d_out;

    cudaFuncSetAttribute(enc_kernel, cudaFuncAttributeMaxDynamicSharedMemorySize, SMEM_BYTES);
    cudaFuncSetAttribute(dec_kernel, cudaFuncAttributeMaxDynamicSharedMemorySize, SMEM_BYTES);
    cudaFuncSetAttribute(blk_mma_kernel<true>,  cudaFuncAttributeMaxDynamicSharedMemorySize, MMA_SMEM);
    cudaFuncSetAttribute(blk_mma_kernel<false>, cudaFuncAttributeMaxDynamicSharedMemorySize, MMA_SMEM);

    detect_idx_kernel<<<1, 256>>>(snd);
    prep_w_kernel<<<896, 512>>>(beW1, beW2, bnW1, bnW2);
    convert_idx_kernel<<<ESTAT, 256>>>(snd, rcv);
    stats_kernel<<<ESTAT + NSTAT, 256>>>(pos, zl, zt);
    enc_kernel<<<EBLK + NBLK, THREADS, SMEM_BYTES>>>(enW1, enb1, enW2, enb2,
                                                     eeW1, eeb1, eeW2, eeb2, zl);
    for (int b = 0; b < 4; b++) {
        blk_mma_kernel<true><<<EBLK, THREADS, MMA_SMEM>>>(beb1 + (size_t)b * HD,
                                                          beb2 + (size_t)b * HD, b);
        blk_mma_kernel<false><<<NBLK, THREADS, MMA_SMEM>>>(bnb1 + (size_t)b * HD,
                                                           bnb2 + (size_t)b * HD, b);
    }
    dec_kernel<<<NBLK, THREADS, SMEM_BYTES>>>(dW1, db1, dW2, db2, zl, zt, out);
    finalize_out_kernel<<<32, 256>>>(out, out_size);
}